// round 10
// baseline (speedup 1.0000x reference)
#include <cuda_runtime.h>
#include <cuda_bf16.h>
#include <stdint.h>

// NearestMean: out[i] = labels[ sum_j (x[i] >= thresholds[j]) ], float32 output.
// R9 post-mortem: __ldcs/__stcs raised regs 32->40, occ 81->62%, kernel SLOWER.
// R10 = R8 body (plain ld/st, regs ~32) + R9's exact-tile/no-predicate/32-bit
// indexing. Pure HBM-bound: floor ~= 1.143GB / ~7.2TB/s ~= 158us kernel.

// ---------- param decode (uniform, negligible at ILP=4 thread counts) ----------
__device__ __forceinline__ float decode_label_word(uint32_t w) {
    if (w == 0u) return 0.0f;
    float f = __uint_as_float(w);
    float af = fabsf(f);
    uint32_t exp = (w >> 23) & 0xFFu;
    if (exp != 0xFFu && af >= 1e-6f && af <= 1e6f) return f;   // plausible float32
    return (float)(int)w;                                       // else int32 bits
}

__device__ __forceinline__ void decode_params(
    const void* __restrict__ thrRaw, const void* __restrict__ labsRaw,
    float& t0, float& t1, float& t2,
    float& l0, float& l1, float& l2, float& l3)
{
    const float* pf = (const float*)thrRaw;
    float a = pf[0], b = pf[1], c = pf[2];
    bool ok = isfinite(a) && isfinite(b) && isfinite(c) &&
              (a < b) && (b < c) && fabsf(a) < 1e8f && fabsf(c) < 1e8f;
    if (!ok) {
        const double* pd = (const double*)thrRaw;
        a = (float)pd[0]; b = (float)pd[1]; c = (float)pd[2];
    }
    t0 = a; t1 = b; t2 = c;

    const uint32_t* lr = (const uint32_t*)labsRaw;
    uint32_t w0 = lr[0], w1 = lr[1], w2 = lr[2], w3 = lr[3];
    if (w1 == 0u && w3 == 0u && (w2 != 0u || w0 != 0u)) {      // int64 signature
        l0 = (float)(int)lr[0];
        l1 = (float)(int)lr[2];
        l2 = (float)(int)lr[4];
        l3 = (float)(int)lr[6];
    } else {
        l0 = decode_label_word(w0);
        l1 = decode_label_word(w1);
        l2 = decode_label_word(w2);
        l3 = decode_label_word(w3);
    }
}

// ---------- hot path ----------
__device__ __forceinline__ float bucket(float v, float t0, float t1, float t2,
                                        float l0, float l1, float l2, float l3)
{
    float r = (v >= t2) ? l3 : l2;
    r = (v >= t1) ? r : l1;
    r = (v >= t0) ? r : l0;
    return r;
}

#define NM_ILP 4

// Exact-tile variant: grid*256*NM_ILP == n4. No bounds checks, 32-bit indexing,
// plain cached loads/stores (keeps regs ~32 -> occ ~80%).
__global__ __launch_bounds__(256) void nm_vec4_exact(
    const float4* __restrict__ x4,
    const void* __restrict__ thrRaw,
    const void* __restrict__ labsRaw,
    float4* __restrict__ out4)
{
    float t0, t1, t2, l0, l1, l2, l3;
    decode_params(thrRaw, labsRaw, t0, t1, t2, l0, l1, l2, l3);

    unsigned base = blockIdx.x * (256u * NM_ILP) + threadIdx.x;

    float4 v[NM_ILP];
    #pragma unroll
    for (int k = 0; k < NM_ILP; k++)
        v[k] = x4[base + (unsigned)k * 256u];   // front-batched LDG.128, MLP=4

    #pragma unroll
    for (int k = 0; k < NM_ILP; k++) {
        float4 r;
        r.x = bucket(v[k].x, t0, t1, t2, l0, l1, l2, l3);
        r.y = bucket(v[k].y, t0, t1, t2, l0, l1, l2, l3);
        r.z = bucket(v[k].z, t0, t1, t2, l0, l1, l2, l3);
        r.w = bucket(v[k].w, t0, t1, t2, l0, l1, l2, l3);
        out4[base + (unsigned)k * 256u] = r;
    }
}

// General bounds-checked variant (fallback for non-divisible n4).
__global__ __launch_bounds__(256) void nm_vec4(
    const float4* __restrict__ x4,
    const void* __restrict__ thrRaw,
    const void* __restrict__ labsRaw,
    float4* __restrict__ out4,
    long long n4)
{
    float t0, t1, t2, l0, l1, l2, l3;
    decode_params(thrRaw, labsRaw, t0, t1, t2, l0, l1, l2, l3);

    long long base = (long long)blockIdx.x * (256 * NM_ILP) + threadIdx.x;

    float4 v[NM_ILP];
    bool ok[NM_ILP];
    #pragma unroll
    for (int k = 0; k < NM_ILP; k++) {
        long long i = base + (long long)k * 256;
        ok[k] = (i < n4);
        if (ok[k]) v[k] = x4[i];
    }

    #pragma unroll
    for (int k = 0; k < NM_ILP; k++) {
        if (ok[k]) {
            long long i = base + (long long)k * 256;
            float4 r;
            r.x = bucket(v[k].x, t0, t1, t2, l0, l1, l2, l3);
            r.y = bucket(v[k].y, t0, t1, t2, l0, l1, l2, l3);
            r.z = bucket(v[k].z, t0, t1, t2, l0, l1, l2, l3);
            r.w = bucket(v[k].w, t0, t1, t2, l0, l1, l2, l3);
            out4[i] = r;
        }
    }
}

__global__ __launch_bounds__(256) void nm_scalar(
    const float* __restrict__ x,
    const void* __restrict__ thrRaw,
    const void* __restrict__ labsRaw,
    float* __restrict__ out,
    long long n)
{
    float t0, t1, t2, l0, l1, l2, l3;
    decode_params(thrRaw, labsRaw, t0, t1, t2, l0, l1, l2, l3);

    long long i = (long long)blockIdx.x * blockDim.x + threadIdx.x;
    if (i >= n) return;
    out[i] = bucket(x[i], t0, t1, t2, l0, l1, l2, l3);
}

extern "C" void kernel_launch(void* const* d_in, const int* in_sizes, int n_in,
                              void* d_out, int out_size)
{
    // Identify inputs by element count: X = largest; thresholds = smaller small
    // array (K-1); labels = larger small array (K).
    int xi = 0;
    for (int k = 1; k < n_in; k++)
        if (in_sizes[k] > in_sizes[xi]) xi = k;

    int ti = -1, li = -1;
    for (int k = 0; k < n_in; k++) {
        if (k == xi) continue;
        if (ti < 0) { ti = k; continue; }
        li = k;
    }
    if (ti >= 0 && li >= 0 && in_sizes[ti] > in_sizes[li]) {
        int tmp = ti; ti = li; li = tmp;
    }
    if (li < 0) li = ti;

    const float* X = (const float*)d_in[xi];
    float* out = (float*)d_out;
    long long n = (long long)in_sizes[xi];

    bool aligned = (((uintptr_t)X & 15u) == 0) && (((uintptr_t)out & 15u) == 0);

    if (aligned && (n % 4 == 0)) {
        long long n4 = n / 4;
        const long long tile = 256LL * NM_ILP;
        if ((n4 % tile) == 0 && (n4 / tile) <= 0x7FFFFFFFLL) {
            unsigned blocks = (unsigned)(n4 / tile);
            nm_vec4_exact<<<blocks, 256>>>(
                (const float4*)X, d_in[ti], d_in[li], (float4*)out);
        } else {
            long long blocks = (n4 + tile - 1) / tile;
            nm_vec4<<<(unsigned)blocks, 256>>>(
                (const float4*)X, d_in[ti], d_in[li], (float4*)out, n4);
        }
    } else {
        long long blocks = (n + 255) / 256;
        nm_scalar<<<(unsigned)blocks, 256>>>(X, d_in[ti], d_in[li], out, n);
    }
}